// round 16
// baseline (speedup 1.0000x reference)
#include <cuda_runtime.h>
#include <cstdint>

// Problem constants
#define B_       8192
#define NROW     40
#define FDIM     256
#define NF       (NROW*FDIM)            // 10240
#define TOTROWS  (B_*NROW)              // 327680
#define TOTELEM  ((size_t)TOTROWS*FDIM) // 83,886,080
#define EPS_     1e-5f

// GEMM tiling: CTA 128x128, KT=16, double-buffered, 256 thr
#define KT   16
#define NSTAGE (FDIM/KT)   // 16

#define BLKB 16      // batches per stat CTA
#define NRMB 8       // batches per norm CTA

// Scratch (device-static: no allocations allowed)
__device__ float g_s[TOTELEM];      // S = X @ W (row-major)  — ONLY big intermediate
__device__ float g_Wt[FDIM*FDIM];   // W rounded to tf32 (row-major [k][n])
__device__ float g_sum[NF];
__device__ float g_sq[NF];
__device__ float g_scale[NF];
__device__ float g_shift[NF];

__device__ __forceinline__ float to_tf32(float x){
    float r;
    asm("cvt.rna.tf32.f32 %0, %1;" : "=f"(r) : "f"(x));
    return r;
}

__device__ __forceinline__ void cpa16(void* smem_dst, const void* gsrc){
    unsigned d = (unsigned)__cvta_generic_to_shared(smem_dst);
    asm volatile("cp.async.cg.shared.global [%0], [%1], 16;" :: "r"(d), "l"(gsrc));
}

__device__ __forceinline__ void mma_tf32(float* c, const unsigned* a, const unsigned* b){
    asm volatile(
        "mma.sync.aligned.m16n8k8.row.col.f32.tf32.tf32.f32 "
        "{%0,%1,%2,%3}, {%4,%5,%6,%7}, {%8,%9}, {%0,%1,%2,%3};\n"
        : "+f"(c[0]), "+f"(c[1]), "+f"(c[2]), "+f"(c[3])
        : "r"(a[0]), "r"(a[1]), "r"(a[2]), "r"(a[3]), "r"(b[0]), "r"(b[1]));
}

// ---------------------------------------------------------------------------
// K0: W -> tf32 (row-major), zero stat accumulators (re-zero every replay).
__global__ void k_prep(const float* __restrict__ W){
    int i = blockIdx.x * 256 + threadIdx.x;
    if (i < FDIM*FDIM) g_Wt[i] = to_tf32(W[i]);
    if (i < NF){ g_sum[i] = 0.f; g_sq[i] = 0.f; }
}

// ---------------------------------------------------------------------------
// K1: S = X @ W  (tf32 mma.sync). A-fragments rna-rounded after LDS.
__global__ __launch_bounds__(256) void k_gemm(const float* __restrict__ X){
    __shared__ float sA[2][128][20];
    __shared__ float sB[2][KT][136];

    int tid  = threadIdx.x;
    int bid  = blockIdx.x;
    int nb   = bid & 1;
    int mb   = bid >> 1;
    size_t rowbase = (size_t)mb * 128;
    int n0   = nb * 128;
    int lane = tid & 31, warp = tid >> 5;
    int wm   = warp >> 1, wn = warp & 1;
    int g    = lane >> 2, t = lane & 3;

    int la_row = tid >> 2;
    int la_col = (tid & 3) * 4;
    int lb_row = tid >> 5;
    int lb_col = (tid & 31) * 4;

    float acc[2][8][4];
    #pragma unroll
    for (int mt = 0; mt < 2; mt++)
        #pragma unroll
        for (int nt = 0; nt < 8; nt++)
            #pragma unroll
            for (int v = 0; v < 4; v++) acc[mt][nt][v] = 0.f;

    auto loadStage = [&](int s, int buf){
        int k0 = s * KT;
        cpa16(&sA[buf][la_row   ][la_col], X + (rowbase + la_row     )*FDIM + k0 + la_col);
        cpa16(&sA[buf][la_row+64][la_col], X + (rowbase + la_row + 64)*FDIM + k0 + la_col);
        cpa16(&sB[buf][lb_row   ][lb_col], g_Wt + (size_t)(k0 + lb_row    )*FDIM + n0 + lb_col);
        cpa16(&sB[buf][lb_row+8 ][lb_col], g_Wt + (size_t)(k0 + lb_row + 8)*FDIM + n0 + lb_col);
    };

    loadStage(0, 0);
    asm volatile("cp.async.commit_group;");

    for (int s = 0; s < NSTAGE; s++){
        int cur = s & 1;
        asm volatile("cp.async.wait_all;" ::: "memory");
        __syncthreads();
        if (s + 1 < NSTAGE){
            loadStage(s + 1, cur ^ 1);
            asm volatile("cp.async.commit_group;");
        }
        #pragma unroll
        for (int k8 = 0; k8 < KT/8; k8++){
            unsigned a[2][4], bf[8][2];
            int kc = k8*8 + t;
            #pragma unroll
            for (int mt = 0; mt < 2; mt++){
                int r0 = wm*32 + mt*16 + g;
                a[mt][0] = __float_as_uint(to_tf32(sA[cur][r0  ][kc  ]));
                a[mt][1] = __float_as_uint(to_tf32(sA[cur][r0+8][kc  ]));
                a[mt][2] = __float_as_uint(to_tf32(sA[cur][r0  ][kc+4]));
                a[mt][3] = __float_as_uint(to_tf32(sA[cur][r0+8][kc+4]));
            }
            #pragma unroll
            for (int nt = 0; nt < 8; nt++){
                int cc = wn*64 + nt*8 + g;
                bf[nt][0] = __float_as_uint(sB[cur][kc  ][cc]);
                bf[nt][1] = __float_as_uint(sB[cur][kc+4][cc]);
            }
            #pragma unroll
            for (int mt = 0; mt < 2; mt++)
                #pragma unroll
                for (int nt = 0; nt < 8; nt++)
                    mma_tf32(acc[mt][nt], a[mt], bf[nt]);
        }
        __syncthreads();
    }

    #pragma unroll
    for (int mt = 0; mt < 2; mt++){
        int r = wm*32 + mt*16 + g;
        #pragma unroll
        for (int nt = 0; nt < 8; nt++){
            int c = n0 + wn*64 + nt*8 + 2*t;
            float2 v0 = make_float2(acc[mt][nt][0], acc[mt][nt][1]);
            float2 v1 = make_float2(acc[mt][nt][2], acc[mt][nt][3]);
            *(float2*)(g_s + (rowbase + r    )*FDIM + c) = v0;
            *(float2*)(g_s + (rowbase + r + 8)*FDIM + c) = v1;
        }
    }
}

// ---------------------------------------------------------------------------
// K2: stats only — y = blockdiag(adj) @ S computed in registers and
// discarded; sum/sq accumulated per thread over 16 batches; spread REDG flush.
__global__ __launch_bounds__(512) void k_blk(const float* __restrict__ adj){
    __shared__ float sadj[BLKB][4][10][10];   // 25.6 KB

    int tid = threadIdx.x;
    int f   = tid & 255;
    int rh  = tid >> 8;            // 0/1
    int b0  = blockIdx.x * BLKB;

    for (int i = tid; i < BLKB*400; i += 512){
        int bb  = i / 400;
        int rem = i % 400;
        int blk = rem / 100;
        int ri  = (rem / 10) % 10;
        int jj  = rem % 10;
        sadj[bb][blk][ri][jj] =
            adj[(size_t)(b0 + bb)*(NROW*NROW) + (size_t)(blk*10 + ri)*NROW + blk*10 + jj];
    }
    __syncthreads();

    int rowoff = rh * 20;

    float sum[20], sq[20];
    #pragma unroll
    for (int i = 0; i < 20; i++){ sum[i] = 0.f; sq[i] = 0.f; }

    for (int bb = 0; bb < BLKB; bb++){
        const float* Sp = g_s + ((size_t)(b0 + bb)*NROW + rowoff)*FDIM + f;
        float x[20];
        #pragma unroll
        for (int j = 0; j < 20; j++) x[j] = Sp[j*FDIM];

        #pragma unroll
        for (int pp = 0; pp < 2; pp++){
            int blk = rh*2 + pp;
            #pragma unroll
            for (int r = 0; r < 10; r++){
                float a = 0.f;
                #pragma unroll
                for (int j = 0; j < 10; j++)
                    a += sadj[bb][blk][r][j] * x[pp*10 + j];
                int ri = pp*10 + r;
                sum[ri] += a;
                sq[ri]  += a*a;
            }
        }
    }

    #pragma unroll
    for (int ri = 0; ri < 20; ri++){
        atomicAdd(&g_sum[(rowoff + ri)*FDIM + f], sum[ri]);
        atomicAdd(&g_sq [(rowoff + ri)*FDIM + f], sq[ri]);
    }
}

// ---------------------------------------------------------------------------
// K3: fold mean/var/gamma/beta -> per-feature scale & shift.
__global__ void k_final(const float* __restrict__ gamma,
                        const float* __restrict__ beta){
    int q = blockIdx.x * 256 + threadIdx.x;   // 0..10239
    float inv = 1.f / (float)B_;
    float mean = g_sum[q] * inv;
    float var  = g_sq[q] * inv - mean*mean;
    int i = q / (10*FDIM);
    float sc = rsqrtf(var + EPS_) * gamma[i*NF + q];
    float bs = beta[q] + beta[NF + q] + beta[2*NF + q] + beta[3*NF + q];
    g_scale[q] = sc;
    g_shift[q] = bs - mean*sc;
}

// ---------------------------------------------------------------------------
// K4: output pass — recompute y from S (+adj) with the SAME FP order as
// k_blk, apply scale/shift, write out. No g_y intermediate.
__global__ __launch_bounds__(512) void k_norm(const float* __restrict__ adj,
                                              float* __restrict__ out){
    __shared__ float sadj[NRMB][4][10][10];   // 12.8 KB

    int tid = threadIdx.x;
    int f   = tid & 255;
    int rh  = tid >> 8;            // 0/1
    int b0  = blockIdx.x * NRMB;

    for (int i = tid; i < NRMB*400; i += 512){
        int bb  = i / 400;
        int rem = i % 400;
        int blk = rem / 100;
        int ri  = (rem / 10) % 10;
        int jj  = rem % 10;
        sadj[bb][blk][ri][jj] =
            adj[(size_t)(b0 + bb)*(NROW*NROW) + (size_t)(blk*10 + ri)*NROW + blk*10 + jj];
    }
    __syncthreads();

    int rowoff = rh * 20;

    // per-thread scale/shift for its 20 rows (L2-hot, loaded once)
    float sc[20], sh[20];
    #pragma unroll
    for (int ri = 0; ri < 20; ri++){
        sc[ri] = g_scale[(rowoff + ri)*FDIM + f];
        sh[ri] = g_shift[(rowoff + ri)*FDIM + f];
    }

    for (int bb = 0; bb < NRMB; bb++){
        size_t base = ((size_t)(b0 + bb)*NROW + rowoff)*FDIM + f;
        const float* Sp = g_s + base;
        float* op = out + base;

        float x[20];
        #pragma unroll
        for (int j = 0; j < 20; j++) x[j] = Sp[j*FDIM];

        #pragma unroll
        for (int pp = 0; pp < 2; pp++){
            int blk = rh*2 + pp;
            #pragma unroll
            for (int r = 0; r < 10; r++){
                float a = 0.f;
                #pragma unroll
                for (int j = 0; j < 10; j++)
                    a += sadj[bb][blk][r][j] * x[pp*10 + j];
                int ri = pp*10 + r;
                op[ri*FDIM] = a * sc[ri] + sh[ri];
            }
        }
    }
}

// ---------------------------------------------------------------------------
extern "C" void kernel_launch(void* const* d_in, const int* in_sizes, int n_in,
                              void* d_out, int out_size){
    const float* inp   = (const float*)d_in[0];
    const float* adj   = (const float*)d_in[1];
    const float* W     = (const float*)d_in[2];
    const float* gamma = (const float*)d_in[3];
    const float* beta  = (const float*)d_in[4];
    float* out = (float*)d_out;

    k_prep <<<256, 256>>>(W);
    k_gemm <<<(TOTROWS/128)*2, 256>>>(inp);
    k_blk  <<<B_/BLKB, 512>>>(adj);
    k_final<<<NF/256, 256>>>(gamma, beta);
    k_norm <<<B_/NRMB, 512>>>(adj, out);
}

// round 17
// speedup vs baseline: 1.1025x; 1.1025x over previous
#include <cuda_runtime.h>
#include <cstdint>

// Problem constants
#define B_       8192
#define NROW     40
#define FDIM     256
#define NF       (NROW*FDIM)            // 10240
#define TOTROWS  (B_*NROW)              // 327680
#define TOTELEM  ((size_t)TOTROWS*FDIM) // 83,886,080
#define EPS_     1e-5f

// GEMM tiling: CTA 128x128, KT=16, double-buffered, 256 thr
#define KT   16
#define NSTAGE (FDIM/KT)   // 16

#define BLKB 16      // batches per stat CTA

// Scratch (device-static: no allocations allowed)
__device__ float g_s[TOTELEM];      // S = X @ W (row-major)
__device__ float g_y[TOTELEM];      // y = blockdiag(adj) @ S
__device__ float g_Wt[FDIM*FDIM];   // W rounded to tf32 (row-major [k][n])
__device__ float g_sum[NF];
__device__ float g_sq[NF];
__device__ float g_scale[NF];
__device__ float g_shift[NF];

__device__ __forceinline__ float to_tf32(float x){
    float r;
    asm("cvt.rna.tf32.f32 %0, %1;" : "=f"(r) : "f"(x));
    return r;
}

__device__ __forceinline__ void cpa16(void* smem_dst, const void* gsrc){
    unsigned d = (unsigned)__cvta_generic_to_shared(smem_dst);
    asm volatile("cp.async.cg.shared.global [%0], [%1], 16;" :: "r"(d), "l"(gsrc));
}

__device__ __forceinline__ void mma_tf32(float* c, const unsigned* a, const unsigned* b){
    asm volatile(
        "mma.sync.aligned.m16n8k8.row.col.f32.tf32.tf32.f32 "
        "{%0,%1,%2,%3}, {%4,%5,%6,%7}, {%8,%9}, {%0,%1,%2,%3};\n"
        : "+f"(c[0]), "+f"(c[1]), "+f"(c[2]), "+f"(c[3])
        : "r"(a[0]), "r"(a[1]), "r"(a[2]), "r"(a[3]), "r"(b[0]), "r"(b[1]));
}

// ---------------------------------------------------------------------------
// K0: W -> tf32 (row-major), zero stat accumulators (re-zero every replay).
__global__ void k_prep(const float* __restrict__ W){
    int i = blockIdx.x * 256 + threadIdx.x;
    if (i < FDIM*FDIM) g_Wt[i] = to_tf32(W[i]);
    if (i < NF){ g_sum[i] = 0.f; g_sq[i] = 0.f; }
}

// ---------------------------------------------------------------------------
// K1: S = X @ W  (tf32 mma.sync). A-fragments rna-rounded after LDS.
__global__ __launch_bounds__(256) void k_gemm(const float* __restrict__ X){
    __shared__ float sA[2][128][20];
    __shared__ float sB[2][KT][136];

    int tid  = threadIdx.x;
    int bid  = blockIdx.x;
    int nb   = bid & 1;
    int mb   = bid >> 1;
    size_t rowbase = (size_t)mb * 128;
    int n0   = nb * 128;
    int lane = tid & 31, warp = tid >> 5;
    int wm   = warp >> 1, wn = warp & 1;
    int g    = lane >> 2, t = lane & 3;

    int la_row = tid >> 2;
    int la_col = (tid & 3) * 4;
    int lb_row = tid >> 5;
    int lb_col = (tid & 31) * 4;

    float acc[2][8][4];
    #pragma unroll
    for (int mt = 0; mt < 2; mt++)
        #pragma unroll
        for (int nt = 0; nt < 8; nt++)
            #pragma unroll
            for (int v = 0; v < 4; v++) acc[mt][nt][v] = 0.f;

    auto loadStage = [&](int s, int buf){
        int k0 = s * KT;
        cpa16(&sA[buf][la_row   ][la_col], X + (rowbase + la_row     )*FDIM + k0 + la_col);
        cpa16(&sA[buf][la_row+64][la_col], X + (rowbase + la_row + 64)*FDIM + k0 + la_col);
        cpa16(&sB[buf][lb_row   ][lb_col], g_Wt + (size_t)(k0 + lb_row    )*FDIM + n0 + lb_col);
        cpa16(&sB[buf][lb_row+8 ][lb_col], g_Wt + (size_t)(k0 + lb_row + 8)*FDIM + n0 + lb_col);
    };

    loadStage(0, 0);
    asm volatile("cp.async.commit_group;");

    for (int s = 0; s < NSTAGE; s++){
        int cur = s & 1;
        asm volatile("cp.async.wait_all;" ::: "memory");
        __syncthreads();
        if (s + 1 < NSTAGE){
            loadStage(s + 1, cur ^ 1);
            asm volatile("cp.async.commit_group;");
        }
        #pragma unroll
        for (int k8 = 0; k8 < KT/8; k8++){
            unsigned a[2][4], bf[8][2];
            int kc = k8*8 + t;
            #pragma unroll
            for (int mt = 0; mt < 2; mt++){
                int r0 = wm*32 + mt*16 + g;
                a[mt][0] = __float_as_uint(to_tf32(sA[cur][r0  ][kc  ]));
                a[mt][1] = __float_as_uint(to_tf32(sA[cur][r0+8][kc  ]));
                a[mt][2] = __float_as_uint(to_tf32(sA[cur][r0  ][kc+4]));
                a[mt][3] = __float_as_uint(to_tf32(sA[cur][r0+8][kc+4]));
            }
            #pragma unroll
            for (int nt = 0; nt < 8; nt++){
                int cc = wn*64 + nt*8 + g;
                bf[nt][0] = __float_as_uint(sB[cur][kc  ][cc]);
                bf[nt][1] = __float_as_uint(sB[cur][kc+4][cc]);
            }
            #pragma unroll
            for (int mt = 0; mt < 2; mt++)
                #pragma unroll
                for (int nt = 0; nt < 8; nt++)
                    mma_tf32(acc[mt][nt], a[mt], bf[nt]);
        }
        __syncthreads();
    }

    #pragma unroll
    for (int mt = 0; mt < 2; mt++){
        int r = wm*32 + mt*16 + g;
        #pragma unroll
        for (int nt = 0; nt < 8; nt++){
            int c = n0 + wn*64 + nt*8 + 2*t;
            float2 v0 = make_float2(acc[mt][nt][0], acc[mt][nt][1]);
            float2 v1 = make_float2(acc[mt][nt][2], acc[mt][nt][3]);
            *(float2*)(g_s + (rowbase + r    )*FDIM + c) = v0;
            *(float2*)(g_s + (rowbase + r + 8)*FDIM + c) = v1;
        }
    }
}

// ---------------------------------------------------------------------------
// K2: y = blockdiag(adj) @ S with fused batch stats, float2 access.
// 512 threads: f2 = tid&127 (float2 column), rq = tid>>7 (diag block 0..3,
// rows rq*10..rq*10+9). Register sum/sq over BLKB batches; spread REDG flush.
__global__ __launch_bounds__(512) void k_blk(const float* __restrict__ adj){
    __shared__ float sadj[BLKB][4][10][10];   // 25.6 KB

    int tid = threadIdx.x;
    int f2  = tid & 127;           // float2 column index
    int rq  = tid >> 7;            // block 0..3
    int b0  = blockIdx.x * BLKB;

    for (int i = tid; i < BLKB*400; i += 512){
        int bb  = i / 400;
        int rem = i % 400;
        int blk = rem / 100;
        int ri  = (rem / 10) % 10;
        int jj  = rem % 10;
        sadj[bb][blk][ri][jj] =
            adj[(size_t)(b0 + bb)*(NROW*NROW) + (size_t)(blk*10 + ri)*NROW + blk*10 + jj];
    }
    __syncthreads();

    int rowoff = rq * 10;

    float2 sum[10], sq[10];
    #pragma unroll
    for (int i = 0; i < 10; i++){
        sum[i] = make_float2(0.f, 0.f);
        sq[i]  = make_float2(0.f, 0.f);
    }

    for (int bb = 0; bb < BLKB; bb++){
        size_t base2 = (((size_t)(b0 + bb)*NROW + rowoff)*FDIM >> 1) + f2;
        const float2* Sp = (const float2*)g_s + base2;
        float2* yp = (float2*)g_y + base2;

        float2 x[10];
        #pragma unroll
        for (int j = 0; j < 10; j++) x[j] = Sp[(size_t)j*(FDIM/2)];

        #pragma unroll
        for (int r = 0; r < 10; r++){
            float ax = 0.f, ay = 0.f;
            #pragma unroll
            for (int j = 0; j < 10; j++){
                float av = sadj[bb][rq][r][j];
                ax += av * x[j].x;
                ay += av * x[j].y;
            }
            yp[(size_t)r*(FDIM/2)] = make_float2(ax, ay);
            sum[r].x += ax;  sum[r].y += ay;
            sq[r].x  += ax*ax; sq[r].y += ay*ay;
        }
    }

    #pragma unroll
    for (int r = 0; r < 10; r++){
        int q = (rowoff + r)*FDIM + f2*2;
        atomicAdd(&g_sum[q    ], sum[r].x);
        atomicAdd(&g_sum[q + 1], sum[r].y);
        atomicAdd(&g_sq [q    ], sq[r].x);
        atomicAdd(&g_sq [q + 1], sq[r].y);
    }
}

// ---------------------------------------------------------------------------
// K3: fold mean/var/gamma/beta -> per-feature scale & shift.
__global__ void k_final(const float* __restrict__ gamma,
                        const float* __restrict__ beta){
    int q = blockIdx.x * 256 + threadIdx.x;   // 0..10239
    float inv = 1.f / (float)B_;
    float mean = g_sum[q] * inv;
    float var  = g_sq[q] * inv - mean*mean;
    int i = q / (10*FDIM);
    float sc = rsqrtf(var + EPS_) * gamma[i*NF + q];
    float bs = beta[q] + beta[NF + q] + beta[2*NF + q] + beta[3*NF + q];
    g_scale[q] = sc;
    g_shift[q] = bs - mean*sc;
}

// ---------------------------------------------------------------------------
// K4: streaming normalize (float4) — R13-measured 79% of HBM.
__global__ __launch_bounds__(256) void k_norm(float* __restrict__ out){
    size_t idx = (size_t)blockIdx.x * 256 + threadIdx.x;  // < 20,971,520
    int q4 = (int)(idx % (NF/4));
    float4 v  = ((const float4*)g_y)[idx];
    float4 sc = ((const float4*)g_scale)[q4];
    float4 sh = ((const float4*)g_shift)[q4];
    float4 o;
    o.x = v.x*sc.x + sh.x;
    o.y = v.y*sc.y + sh.y;
    o.z = v.z*sc.z + sh.z;
    o.w = v.w*sc.w + sh.w;
    ((float4*)out)[idx] = o;
}

// ---------------------------------------------------------------------------
extern "C" void kernel_launch(void* const* d_in, const int* in_sizes, int n_in,
                              void* d_out, int out_size){
    const float* inp   = (const float*)d_in[0];
    const float* adj   = (const float*)d_in[1];
    const float* W     = (const float*)d_in[2];
    const float* gamma = (const float*)d_in[3];
    const float* beta  = (const float*)d_in[4];
    float* out = (float*)d_out;

    k_prep <<<256, 256>>>(W);
    k_gemm <<<(TOTROWS/128)*2, 256>>>(inp);
    k_blk  <<<B_/BLKB, 512>>>(adj);
    k_final<<<NF/256, 256>>>(gamma, beta);
    k_norm <<<(unsigned)(TOTELEM/4/256), 256>>>(out);
}